// round 1
// baseline (speedup 1.0000x reference)
#include <cuda_runtime.h>
#include <cstdint>

#define N_NODES 100000
#define N_EDGES 1600000
#define D 64
#define D4 16              // D in float4 units
#define BN_EPS 1e-5f

// ---------------- scratch (no allocations allowed) ----------------
__device__ float g_h [N_NODES * D];   // (1+eps)*x + neigh
__device__ float g_y [N_NODES * D];   // MLP output (pre-BN)
__device__ float g_sum[D];
__device__ float g_sq [D];
__device__ float g_scale[D];          // gamma * rsqrt(var+eps)
__device__ float g_shift[D];          // beta - mean*scale

// ---------------- k1: h = (1+eps)*features ; zero BN sums ----------------
__global__ void k_init(const float4* __restrict__ feat4, const float* __restrict__ eps)
{
    if (blockIdx.x == 0 && threadIdx.x < D) {
        g_sum[threadIdx.x] = 0.f;
        g_sq [threadIdx.x] = 0.f;
    }
    float se = 1.0f + *eps;
    float4* h4 = reinterpret_cast<float4*>(g_h);
    int total = N_NODES * D4;
    for (int i = blockIdx.x * blockDim.x + threadIdx.x; i < total; i += gridDim.x * blockDim.x) {
        float4 v = feat4[i];
        v.x *= se; v.y *= se; v.z *= se; v.w *= se;
        h4[i] = v;
    }
}

// ---------------- k2: edge scatter: h[dst] += features[src] ----------------
__global__ void k_scatter(const float4* __restrict__ feat4,
                          const int* __restrict__ src,
                          const int* __restrict__ dst)
{
    int idx = blockIdx.x * blockDim.x + threadIdx.x;       // one (edge, float4-lane)
    if (idx >= N_EDGES * D4) return;
    int e    = idx >> 4;
    int lane = idx & 15;
    int s = src[e];
    int d = dst[e];
    float4 v = feat4[s * D4 + lane];
    float* p = g_h + (size_t)d * D + lane * 4;
    asm volatile("red.global.add.v4.f32 [%0], {%1, %2, %3, %4};"
                 :: "l"(p), "f"(v.x), "f"(v.y), "f"(v.z), "f"(v.w)
                 : "memory");
}

// ---------------- k3: y = relu(h@W1+b1)@W2 + b2 ; accumulate BN sums ------
// block = 256 threads handles 64 rows. thread (r = tid/4, c0 = (tid%3)*16..)
__global__ __launch_bounds__(256) void k_mlp(const float* __restrict__ W1,
                                             const float* __restrict__ b1,
                                             const float* __restrict__ W2,
                                             const float* __restrict__ b2)
{
    __shared__ float hs[64][65];     // rows tile (padded: conflict-free column reads)
    __shared__ float ws[64][64];     // W1 then reloaded with W2
    __shared__ float bs1[64], bs2[64];
    __shared__ float ssum[64], ssq[64];

    int tid  = threadIdx.x;
    int base = blockIdx.x * 64;

    for (int i = tid; i < 4096; i += 256)
        ws[i >> 6][i & 63] = W1[i];
    if (tid < 64) {
        bs1[tid] = b1[tid];
        bs2[tid] = b2[tid];
        ssum[tid] = 0.f;
        ssq [tid] = 0.f;
    }
    for (int i = tid; i < 4096; i += 256) {
        int r = i >> 6, c = i & 63;
        int row = base + r;
        hs[r][c] = (row < N_NODES) ? g_h[(size_t)row * D + c] : 0.f;
    }
    __syncthreads();

    int r  = tid >> 2;           // 0..63
    int c0 = (tid & 3) * 16;     // 0,16,32,48

    float t[16];
    #pragma unroll
    for (int j = 0; j < 16; j++) t[j] = bs1[c0 + j];
    #pragma unroll 8
    for (int k = 0; k < 64; k++) {
        float hv = hs[r][k];
        #pragma unroll
        for (int j = 0; j < 16; j++) t[j] = fmaf(hv, ws[k][c0 + j], t[j]);
    }
    #pragma unroll
    for (int j = 0; j < 16; j++) t[j] = fmaxf(t[j], 0.f);

    __syncthreads();                       // all phase-1 reads done
    #pragma unroll
    for (int j = 0; j < 16; j++) hs[r][c0 + j] = t[j];   // t tile into hs
    for (int i = tid; i < 4096; i += 256)                // reload ws with W2
        ws[i >> 6][i & 63] = W2[i];
    __syncthreads();

    float o[16];
    #pragma unroll
    for (int j = 0; j < 16; j++) o[j] = bs2[c0 + j];
    #pragma unroll 8
    for (int k = 0; k < 64; k++) {
        float tv = hs[r][k];
        #pragma unroll
        for (int j = 0; j < 16; j++) o[j] = fmaf(tv, ws[k][c0 + j], o[j]);
    }

    int row = base + r;
    if (row < N_NODES) {
        float4* y4 = reinterpret_cast<float4*>(g_y + (size_t)row * D + c0);
        #pragma unroll
        for (int q = 0; q < 4; q++)
            y4[q] = make_float4(o[q*4+0], o[q*4+1], o[q*4+2], o[q*4+3]);
        #pragma unroll
        for (int j = 0; j < 16; j++) {
            atomicAdd(&ssum[c0 + j], o[j]);
            atomicAdd(&ssq [c0 + j], o[j] * o[j]);
        }
    }
    __syncthreads();
    if (tid < 64) {
        atomicAdd(&g_sum[tid], ssum[tid]);
        atomicAdd(&g_sq [tid], ssq [tid]);
    }
}

// ---------------- k4: finalize BN coefficients ----------------
__global__ void k_bnfin(const float* __restrict__ gamma, const float* __restrict__ beta)
{
    int c = threadIdx.x;
    if (c >= D) return;
    float inv_n = 1.0f / (float)N_NODES;
    float mean = g_sum[c] * inv_n;
    float var  = g_sq[c] * inv_n - mean * mean;
    float sc   = gamma[c] * rsqrtf(var + BN_EPS);
    g_scale[c] = sc;
    g_shift[c] = beta[c] - mean * sc;
}

// ---------------- k5: out = features + relu(y*scale + shift) ----------------
__global__ void k_epi(const float4* __restrict__ feat4, float4* __restrict__ out4)
{
    const float4* y4 = reinterpret_cast<const float4*>(g_y);
    const float4* sc4 = reinterpret_cast<const float4*>(g_scale);
    const float4* sh4 = reinterpret_cast<const float4*>(g_shift);
    int total = N_NODES * D4;
    for (int i = blockIdx.x * blockDim.x + threadIdx.x; i < total; i += gridDim.x * blockDim.x) {
        int c4 = i & 15;
        float4 y = y4[i];
        float4 s = sc4[c4];
        float4 t = sh4[c4];
        float4 f = feat4[i];
        float4 r;
        r.x = f.x + fmaxf(fmaf(y.x, s.x, t.x), 0.f);
        r.y = f.y + fmaxf(fmaf(y.y, s.y, t.y), 0.f);
        r.z = f.z + fmaxf(fmaf(y.z, s.z, t.z), 0.f);
        r.w = f.w + fmaxf(fmaf(y.w, s.w, t.w), 0.f);
        out4[i] = r;
    }
}

extern "C" void kernel_launch(void* const* d_in, const int* in_sizes, int n_in,
                              void* d_out, int out_size)
{
    const float4* feat4 = (const float4*)d_in[0];
    const int*    src   = (const int*)  d_in[1];
    const int*    dst   = (const int*)  d_in[2];
    const float*  eps   = (const float*)d_in[3];
    const float*  W1    = (const float*)d_in[4];
    const float*  b1    = (const float*)d_in[5];
    const float*  W2    = (const float*)d_in[6];
    const float*  b2    = (const float*)d_in[7];
    const float*  gamma = (const float*)d_in[8];
    const float*  beta  = (const float*)d_in[9];
    float4* out4 = (float4*)d_out;

    int elem4 = N_NODES * D4;                       // 1.6M float4 items
    int g1 = (elem4 + 255) / 256;                   // 6250
    k_init<<<g1, 256>>>(feat4, eps);

    int g2 = (N_EDGES * D4 + 255) / 256;            // 100000
    k_scatter<<<g2, 256>>>(feat4, src, dst);

    int g3 = (N_NODES + 63) / 64;                   // 1563
    k_mlp<<<g3, 256>>>(W1, b1, W2, b2);

    k_bnfin<<<1, 64>>>(gamma, beta);

    k_epi<<<g1, 256>>>(feat4, out4);
}

// round 2
// speedup vs baseline: 1.0770x; 1.0770x over previous
#include <cuda_runtime.h>
#include <cstdint>

#define N_NODES 100000
#define N_EDGES 1600000
#define D 64
#define D4 16
#define BN_EPS 1e-5f
#define NB_SCAN ((N_NODES + 255) / 256)   // 391

// ---------------- scratch ----------------
__device__ float g_h [N_NODES * D];
__device__ float g_y [N_NODES * D];
__device__ int   g_deg[N_NODES];
__device__ int   g_row[N_NODES + 1];
__device__ int   g_pos[N_NODES];
__device__ int   g_srt[N_EDGES];          // src sorted by dst
__device__ int   g_blk[NB_SCAN];
__device__ float g_sum[D];
__device__ float g_sq [D];
__device__ float g_scale[D];
__device__ float g_shift[D];

// ---------------- zero degree + BN sums ----------------
__global__ void k_zero()
{
    int i = blockIdx.x * blockDim.x + threadIdx.x;
    if (i < N_NODES) g_deg[i] = 0;
    if (i < D) { g_sum[i] = 0.f; g_sq[i] = 0.f; }
}

// ---------------- degree histogram ----------------
__global__ void k_hist(const int* __restrict__ dst)
{
    int e = blockIdx.x * blockDim.x + threadIdx.x;
    if (e < N_EDGES) atomicAdd(&g_deg[dst[e]], 1);
}

// ---------------- scan A: per-block sums ----------------
__global__ __launch_bounds__(256) void k_scanA()
{
    __shared__ int sm[256];
    int i = blockIdx.x * 256 + threadIdx.x;
    int d = (i < N_NODES) ? g_deg[i] : 0;
    sm[threadIdx.x] = d;
    __syncthreads();
    for (int off = 128; off > 0; off >>= 1) {
        if (threadIdx.x < off) sm[threadIdx.x] += sm[threadIdx.x + off];
        __syncthreads();
    }
    if (threadIdx.x == 0) g_blk[blockIdx.x] = sm[0];
}

// ---------------- scan B: exclusive scan of block sums ----------------
__global__ __launch_bounds__(512) void k_scanB()
{
    __shared__ int sm[512];
    int t = threadIdx.x;
    sm[t] = (t < NB_SCAN) ? g_blk[t] : 0;
    __syncthreads();
    for (int off = 1; off < 512; off <<= 1) {
        int v = (t >= off) ? sm[t - off] : 0;
        __syncthreads();
        sm[t] += v;
        __syncthreads();
    }
    if (t < NB_SCAN) g_blk[t] = sm[t] - ((t < NB_SCAN) ? g_blk[t] : 0) + 0; // placeholder, fixed below
    // write exclusive: inclusive - own value. Need own value again:
    __syncthreads();
    if (t == 0) g_row[N_NODES] = N_EDGES;
}

// scanB above is awkward; do it cleanly with a second smem buffer instead.
__global__ __launch_bounds__(512) void k_scanB2()
{
    __shared__ int inval[512];
    __shared__ int sm[512];
    int t = threadIdx.x;
    int v = (t < NB_SCAN) ? g_blk[t] : 0;
    inval[t] = v;
    sm[t] = v;
    __syncthreads();
    for (int off = 1; off < 512; off <<= 1) {
        int u = (t >= off) ? sm[t - off] : 0;
        __syncthreads();
        sm[t] += u;
        __syncthreads();
    }
    if (t < NB_SCAN) g_blk[t] = sm[t] - inval[t];   // exclusive
    if (t == 0) g_row[N_NODES] = N_EDGES;
}

// ---------------- scan C: row offsets + cursors ----------------
__global__ __launch_bounds__(256) void k_scanC()
{
    __shared__ int sm[256];
    int i = blockIdx.x * 256 + threadIdx.x;
    int t = threadIdx.x;
    int d = (i < N_NODES) ? g_deg[i] : 0;
    sm[t] = d;
    __syncthreads();
    for (int off = 1; off < 256; off <<= 1) {
        int u = (t >= off) ? sm[t - off] : 0;
        __syncthreads();
        sm[t] += u;
        __syncthreads();
    }
    if (i < N_NODES) {
        int row = g_blk[blockIdx.x] + sm[t] - d;    // exclusive prefix
        g_row[i] = row;
        g_pos[i] = row;
    }
}

// ---------------- permutation: bucket src by dst ----------------
__global__ void k_perm(const int* __restrict__ src, const int* __restrict__ dst)
{
    int e = blockIdx.x * blockDim.x + threadIdx.x;
    if (e >= N_EDGES) return;
    int p = atomicAdd(&g_pos[dst[e]], 1);
    g_srt[p] = src[e];
}

// ---------------- gather: h = (1+eps)*x + sum_{src in N(dst)} x[src] ------
__global__ __launch_bounds__(256) void k_gather(const float4* __restrict__ feat4,
                                                const float* __restrict__ eps)
{
    int t = threadIdx.x;
    int node = blockIdx.x * 16 + (t >> 4);
    int lane = t & 15;
    float se = 1.0f + *eps;

    int rs = g_row[node];
    int re = g_row[node + 1];

    float4 a = feat4[node * D4 + lane];
    a.x *= se; a.y *= se; a.z *= se; a.w *= se;

    for (int base = rs; base < re; base += 16) {
        int cnt = re - base;
        #pragma unroll
        for (int j = 0; j < 16; j++) {
            if (j < cnt) {
                int s = g_srt[base + j];
                float4 v = feat4[s * D4 + lane];
                a.x += v.x; a.y += v.y; a.z += v.z; a.w += v.w;
            }
        }
    }
    reinterpret_cast<float4*>(g_h)[node * D4 + lane] = a;
}

// ---------------- MLP + BN stats ----------------
__global__ __launch_bounds__(256) void k_mlp(const float* __restrict__ W1,
                                             const float* __restrict__ b1,
                                             const float* __restrict__ W2,
                                             const float* __restrict__ b2)
{
    __shared__ float hs[64][65];
    __shared__ float ws[4096];
    __shared__ float bs1[64], bs2[64];
    __shared__ float ssum[64], ssq[64];

    int tid  = threadIdx.x;
    int base = blockIdx.x * 64;

    for (int i = tid; i < 4096; i += 256) ws[i] = W1[i];
    if (tid < 64) {
        bs1[tid] = b1[tid];
        bs2[tid] = b2[tid];
        ssum[tid] = 0.f;
        ssq [tid] = 0.f;
    }
    {
        const float4* hg = reinterpret_cast<const float4*>(g_h) + (size_t)base * D4;
        for (int i = tid; i < 1024; i += 256) {       // 64 rows x 16 float4
            int r = i >> 4, c4 = i & 15;
            float4 v = (base + r < N_NODES) ? hg[r * D4 + c4] : make_float4(0,0,0,0);
            hs[r][c4*4+0] = v.x; hs[r][c4*4+1] = v.y;
            hs[r][c4*4+2] = v.z; hs[r][c4*4+3] = v.w;
        }
    }
    __syncthreads();

    int r  = tid >> 2;
    int c0 = (tid & 3) * 16;
    int c4 = c0 >> 2;
    const float4* wv = reinterpret_cast<const float4*>(ws);

    float t[16];
    #pragma unroll
    for (int j = 0; j < 16; j++) t[j] = bs1[c0 + j];
    #pragma unroll 4
    for (int k = 0; k < 64; k++) {
        float hv = hs[r][k];
        float4 w0 = wv[k*16 + c4 + 0];
        float4 w1 = wv[k*16 + c4 + 1];
        float4 w2 = wv[k*16 + c4 + 2];
        float4 w3 = wv[k*16 + c4 + 3];
        t[0]  = fmaf(hv, w0.x, t[0]);  t[1]  = fmaf(hv, w0.y, t[1]);
        t[2]  = fmaf(hv, w0.z, t[2]);  t[3]  = fmaf(hv, w0.w, t[3]);
        t[4]  = fmaf(hv, w1.x, t[4]);  t[5]  = fmaf(hv, w1.y, t[5]);
        t[6]  = fmaf(hv, w1.z, t[6]);  t[7]  = fmaf(hv, w1.w, t[7]);
        t[8]  = fmaf(hv, w2.x, t[8]);  t[9]  = fmaf(hv, w2.y, t[9]);
        t[10] = fmaf(hv, w2.z, t[10]); t[11] = fmaf(hv, w2.w, t[11]);
        t[12] = fmaf(hv, w3.x, t[12]); t[13] = fmaf(hv, w3.y, t[13]);
        t[14] = fmaf(hv, w3.z, t[14]); t[15] = fmaf(hv, w3.w, t[15]);
    }
    #pragma unroll
    for (int j = 0; j < 16; j++) t[j] = fmaxf(t[j], 0.f);

    __syncthreads();
    #pragma unroll
    for (int j = 0; j < 16; j++) hs[r][c0 + j] = t[j];
    for (int i = tid; i < 4096; i += 256) ws[i] = W2[i];
    __syncthreads();

    float o[16];
    #pragma unroll
    for (int j = 0; j < 16; j++) o[j] = bs2[c0 + j];
    #pragma unroll 4
    for (int k = 0; k < 64; k++) {
        float tv = hs[r][k];
        float4 w0 = wv[k*16 + c4 + 0];
        float4 w1 = wv[k*16 + c4 + 1];
        float4 w2 = wv[k*16 + c4 + 2];
        float4 w3 = wv[k*16 + c4 + 3];
        o[0]  = fmaf(tv, w0.x, o[0]);  o[1]  = fmaf(tv, w0.y, o[1]);
        o[2]  = fmaf(tv, w0.z, o[2]);  o[3]  = fmaf(tv, w0.w, o[3]);
        o[4]  = fmaf(tv, w1.x, o[4]);  o[5]  = fmaf(tv, w1.y, o[5]);
        o[6]  = fmaf(tv, w1.z, o[6]);  o[7]  = fmaf(tv, w1.w, o[7]);
        o[8]  = fmaf(tv, w2.x, o[8]);  o[9]  = fmaf(tv, w2.y, o[9]);
        o[10] = fmaf(tv, w2.z, o[10]); o[11] = fmaf(tv, w2.w, o[11]);
        o[12] = fmaf(tv, w3.x, o[12]); o[13] = fmaf(tv, w3.y, o[13]);
        o[14] = fmaf(tv, w3.z, o[14]); o[15] = fmaf(tv, w3.w, o[15]);
    }

    int row = base + r;
    if (row < N_NODES) {
        float4* y4 = reinterpret_cast<float4*>(g_y + (size_t)row * D + c0);
        #pragma unroll
        for (int q = 0; q < 4; q++)
            y4[q] = make_float4(o[q*4+0], o[q*4+1], o[q*4+2], o[q*4+3]);
        #pragma unroll
        for (int j = 0; j < 16; j++) {
            atomicAdd(&ssum[c0 + j], o[j]);
            atomicAdd(&ssq [c0 + j], o[j] * o[j]);
        }
    }
    __syncthreads();
    if (tid < 64) {
        atomicAdd(&g_sum[tid], ssum[tid]);
        atomicAdd(&g_sq [tid], ssq [tid]);
    }
}

// ---------------- BN finalize ----------------
__global__ void k_bnfin(const float* __restrict__ gamma, const float* __restrict__ beta)
{
    int c = threadIdx.x;
    if (c >= D) return;
    float inv_n = 1.0f / (float)N_NODES;
    float mean = g_sum[c] * inv_n;
    float var  = g_sq[c] * inv_n - mean * mean;
    float sc   = gamma[c] * rsqrtf(var + BN_EPS);
    g_scale[c] = sc;
    g_shift[c] = beta[c] - mean * sc;
}

// ---------------- epilogue ----------------
__global__ void k_epi(const float4* __restrict__ feat4, float4* __restrict__ out4)
{
    const float4* y4 = reinterpret_cast<const float4*>(g_y);
    const float4* sc4 = reinterpret_cast<const float4*>(g_scale);
    const float4* sh4 = reinterpret_cast<const float4*>(g_shift);
    int total = N_NODES * D4;
    for (int i = blockIdx.x * blockDim.x + threadIdx.x; i < total; i += gridDim.x * blockDim.x) {
        int c4 = i & 15;
        float4 y = y4[i];
        float4 s = sc4[c4];
        float4 t = sh4[c4];
        float4 f = feat4[i];
        float4 r;
        r.x = f.x + fmaxf(fmaf(y.x, s.x, t.x), 0.f);
        r.y = f.y + fmaxf(fmaf(y.y, s.y, t.y), 0.f);
        r.z = f.z + fmaxf(fmaf(y.z, s.z, t.z), 0.f);
        r.w = f.w + fmaxf(fmaf(y.w, s.w, t.w), 0.f);
        out4[i] = r;
    }
}

extern "C" void kernel_launch(void* const* d_in, const int* in_sizes, int n_in,
                              void* d_out, int out_size)
{
    const float4* feat4 = (const float4*)d_in[0];
    const int*    src   = (const int*)  d_in[1];
    const int*    dst   = (const int*)  d_in[2];
    const float*  eps   = (const float*)d_in[3];
    const float*  W1    = (const float*)d_in[4];
    const float*  b1    = (const float*)d_in[5];
    const float*  W2    = (const float*)d_in[6];
    const float*  b2    = (const float*)d_in[7];
    const float*  gamma = (const float*)d_in[8];
    const float*  beta  = (const float*)d_in[9];
    float4* out4 = (float4*)d_out;

    int ge = (N_EDGES + 255) / 256;        // 6250
    int gn = (N_NODES + 255) / 256;        // 391

    k_zero <<<gn, 256>>>();
    k_hist <<<ge, 256>>>(dst);
    k_scanA<<<NB_SCAN, 256>>>();
    k_scanB2<<<1, 512>>>();
    k_scanC<<<NB_SCAN, 256>>>();
    k_perm <<<ge, 256>>>(src, dst);
    k_gather<<<N_NODES / 16, 256>>>(feat4, eps);
    k_mlp  <<<(N_NODES + 63) / 64, 256>>>(W1, b1, W2, b2);
    k_bnfin<<<1, 64>>>(gamma, beta);
    k_epi  <<<(N_NODES * D4 + 255) / 256, 256>>>(feat4, out4);
}